// round 1
// baseline (speedup 1.0000x reference)
#include <cuda_runtime.h>
#include <math.h>

// Problem dims
#define TT 256
#define BB 64
#define HH 1024
#define G4 4096            // 4*HH
#define MM (TT*BB)         // 16384

// ---------------------------------------------------------------------------
// Scratch (device globals: allocation-free per harness rules)
// ---------------------------------------------------------------------------
__device__ float g_xg[(size_t)MM * G4];     // (T,B,4H) precomputed input gates
__device__ float g_out5[(size_t)MM * HH];   // layer-5 output (incl. residual)
__device__ float g_h[2][BB * HH];           // ping-pong hidden state
__device__ float g_c[BB * HH];              // cell state

// ---------------------------------------------------------------------------
// Zero h/c before each layer's recurrence
// ---------------------------------------------------------------------------
__global__ void init_state_kernel() {
    int i = blockIdx.x * blockDim.x + threadIdx.x;
    if (i < BB * HH) {
        g_h[0][i] = 0.f;
        g_h[1][i] = 0.f;
        g_c[i]    = 0.f;
    }
}

// ---------------------------------------------------------------------------
// Input GEMM: XG[m][n] = sum_k X[m][k]*W[n][k] + b1[n] + b2[n]
// M=16384, N=4096, K=1024. 128x128 CTA tile, BK=8, 8x8 per thread.
// ---------------------------------------------------------------------------
__global__ __launch_bounds__(256)
void gemm_xg_kernel(const float* __restrict__ X,
                    const float* __restrict__ W,
                    const float* __restrict__ b1,
                    const float* __restrict__ b2,
                    float* __restrict__ XG)
{
    __shared__ float As[8][128];
    __shared__ float Bs[8][128];

    const int tid = threadIdx.x;
    const int m0 = blockIdx.y * 128;
    const int n0 = blockIdx.x * 128;

    // global->smem load mapping: 128 rows x 8 k, one float4 per thread
    const int lr = tid >> 1;          // 0..127
    const int lc = (tid & 1) * 4;     // 0 or 4
    const float* Ap = X + (size_t)(m0 + lr) * HH + lc;
    const float* Bp = W + (size_t)(n0 + lr) * HH + lc;

    // compute mapping: 16x16 thread grid, 8x8 micro-tile
    const int tx = tid & 15;          // n-subtile
    const int ty = tid >> 4;          // m-subtile

    float acc[8][8];
#pragma unroll
    for (int i = 0; i < 8; i++)
#pragma unroll
        for (int j = 0; j < 8; j++) acc[i][j] = 0.f;

    for (int k0 = 0; k0 < HH; k0 += 8) {
        float4 a4 = *(const float4*)(Ap + k0);
        float4 b4 = *(const float4*)(Bp + k0);
        __syncthreads();
        As[lc+0][lr] = a4.x; As[lc+1][lr] = a4.y;
        As[lc+2][lr] = a4.z; As[lc+3][lr] = a4.w;
        Bs[lc+0][lr] = b4.x; Bs[lc+1][lr] = b4.y;
        Bs[lc+2][lr] = b4.z; Bs[lc+3][lr] = b4.w;
        __syncthreads();
#pragma unroll
        for (int kk = 0; kk < 8; kk++) {
            float a[8], b[8];
            float4 t0 = *(const float4*)&As[kk][ty*8];
            float4 t1 = *(const float4*)&As[kk][ty*8 + 4];
            float4 u0 = *(const float4*)&Bs[kk][tx*8];
            float4 u1 = *(const float4*)&Bs[kk][tx*8 + 4];
            a[0]=t0.x; a[1]=t0.y; a[2]=t0.z; a[3]=t0.w;
            a[4]=t1.x; a[5]=t1.y; a[6]=t1.z; a[7]=t1.w;
            b[0]=u0.x; b[1]=u0.y; b[2]=u0.z; b[3]=u0.w;
            b[4]=u1.x; b[5]=u1.y; b[6]=u1.z; b[7]=u1.w;
#pragma unroll
            for (int i = 0; i < 8; i++)
#pragma unroll
                for (int j = 0; j < 8; j++)
                    acc[i][j] += a[i] * b[j];
        }
    }

#pragma unroll
    for (int i = 0; i < 8; i++) {
        const int m = m0 + ty*8 + i;
        float* outp = XG + (size_t)m * G4 + n0 + tx*8;
#pragma unroll
        for (int j = 0; j < 8; j++) {
            const int n = n0 + tx*8 + j;
            outp[j] = acc[i][j] + b1[n] + b2[n];
        }
    }
}

// ---------------------------------------------------------------------------
// One LSTM timestep. Grid = 128 CTAs; CTA `jb` owns hidden columns
// j = jb*8 .. jb*8+7 and their 4 gate rows {g*H + j}. Computes
// gates = xg_t + h_in @ w_hh^T for its 64x32 tile, then fused pointwise
// update of c, h_out, out_t (out_t = h_new + residual).
// ---------------------------------------------------------------------------
__global__ __launch_bounds__(256)
void lstm_step_kernel(const float* __restrict__ xg_t,   // (B, 4H)
                      const float* __restrict__ w_hh,   // (4H, H)
                      const float* __restrict__ h_in,   // (B, H)
                      float* __restrict__ h_out,        // (B, H)
                      float* __restrict__ c,            // (B, H)
                      const float* __restrict__ res_t,  // (B, H) residual
                      float* __restrict__ out_t)        // (B, H)
{
    const int jb  = blockIdx.x;        // 0..127
    const int tid = threadIdx.x;

    __shared__ float hs[32][68];       // [kk][b], padded (16B-aligned rows)
    __shared__ float ws[32][33];       // [kk][g*8+jj]
    __shared__ float gs[64][33];       // gates [b][g*8+jj]

    // compute mapping: col = gate-col (g*8+jj), thread owns 8 batch rows
    const int col = tid & 31;
    const int b0  = (tid >> 5) * 8;    // 0,8,...,56

    float acc[8];
#pragma unroll
    for (int r = 0; r < 8; r++) acc[r] = 0.f;

    // loader mappings
    const int hr  = tid >> 2;             // batch row 0..63
    const int hc  = (tid & 3) * 8;        // k offset 0,8,16,24
    const int wr  = tid >> 3;             // 0..31 = g*8+jj
    const int wc  = (tid & 7) * 4;        // k offset
    const size_t wrow = (size_t)((wr >> 3) * HH + jb * 8 + (wr & 7)) * HH;

    for (int k0 = 0; k0 < HH; k0 += 32) {
        __syncthreads();
        // h tile: 64 rows x 32 k
        float4 v0 = *(const float4*)(h_in + (size_t)hr * HH + k0 + hc);
        float4 v1 = *(const float4*)(h_in + (size_t)hr * HH + k0 + hc + 4);
        hs[hc+0][hr] = v0.x; hs[hc+1][hr] = v0.y;
        hs[hc+2][hr] = v0.z; hs[hc+3][hr] = v0.w;
        hs[hc+4][hr] = v1.x; hs[hc+5][hr] = v1.y;
        hs[hc+6][hr] = v1.z; hs[hc+7][hr] = v1.w;
        // w tile: 32 gate-rows x 32 k
        float4 wv = *(const float4*)(w_hh + wrow + k0 + wc);
        ws[wc+0][wr] = wv.x; ws[wc+1][wr] = wv.y;
        ws[wc+2][wr] = wv.z; ws[wc+3][wr] = wv.w;
        __syncthreads();
#pragma unroll
        for (int kk = 0; kk < 32; kk++) {
            const float w = ws[kk][col];
            float4 hA = *(const float4*)&hs[kk][b0];
            float4 hB = *(const float4*)&hs[kk][b0 + 4];
            acc[0] += hA.x * w; acc[1] += hA.y * w;
            acc[2] += hA.z * w; acc[3] += hA.w * w;
            acc[4] += hB.x * w; acc[5] += hB.y * w;
            acc[6] += hB.z * w; acc[7] += hB.w * w;
        }
    }

    __syncthreads();
#pragma unroll
    for (int r = 0; r < 8; r++) gs[b0 + r][col] = acc[r];
    __syncthreads();

    // pointwise: 512 (b, jj) pairs, 2 per thread
#pragma unroll
    for (int p = tid; p < 512; p += 256) {
        const int b  = p >> 3;
        const int jj = p & 7;
        const int j  = jb * 8 + jj;
        const size_t idx = (size_t)b * HH + j;
        const size_t xgb = (size_t)b * G4 + j;

        float i_ = gs[b][0*8 + jj] + xg_t[xgb];
        float f_ = gs[b][1*8 + jj] + xg_t[xgb + HH];
        float g_ = gs[b][2*8 + jj] + xg_t[xgb + 2*HH];
        float o_ = gs[b][3*8 + jj] + xg_t[xgb + 3*HH];

        i_ = 1.f / (1.f + __expf(-i_));
        f_ = 1.f / (1.f + __expf(-f_));
        g_ = tanhf(g_);
        o_ = 1.f / (1.f + __expf(-o_));

        const float cv = f_ * c[idx] + i_ * g_;
        c[idx] = cv;
        const float hv = o_ * tanhf(cv);
        h_out[idx] = hv;
        out_t[idx] = hv + res_t[idx];
    }
}

// ---------------------------------------------------------------------------
// Host launch: layer5 (gemm + 256 steps) then layer6. All graph-capturable.
// ---------------------------------------------------------------------------
extern "C" void kernel_launch(void* const* d_in, const int* in_sizes, int n_in,
                              void* d_out, int out_size)
{
    (void)in_sizes; (void)n_in; (void)out_size;
    const float* x     = (const float*)d_in[0];
    const float* w_ih5 = (const float*)d_in[1];
    const float* w_hh5 = (const float*)d_in[2];
    const float* b_ih5 = (const float*)d_in[3];
    const float* b_hh5 = (const float*)d_in[4];
    const float* w_ih6 = (const float*)d_in[5];
    const float* w_hh6 = (const float*)d_in[6];
    const float* b_ih6 = (const float*)d_in[7];
    const float* b_hh6 = (const float*)d_in[8];
    float* out = (float*)d_out;

    float *xg, *out5, *hbuf, *cbuf;
    cudaGetSymbolAddress((void**)&xg,   g_xg);
    cudaGetSymbolAddress((void**)&out5, g_out5);
    cudaGetSymbolAddress((void**)&hbuf, g_h);
    cudaGetSymbolAddress((void**)&cbuf, g_c);
    float* h0 = hbuf;
    float* h1 = hbuf + BB * HH;

    const dim3 gemm_grid(G4 / 128, MM / 128);   // (32, 128)

    // ---- Layer 5 ----
    init_state_kernel<<<(BB*HH + 1023)/1024, 1024>>>();
    gemm_xg_kernel<<<gemm_grid, 256>>>(x, w_ih5, b_ih5, b_hh5, xg);
    for (int t = 0; t < TT; t++) {
        const float* hin  = (t & 1) ? h1 : h0;
        float*       hout = (t & 1) ? h0 : h1;
        lstm_step_kernel<<<128, 256>>>(
            xg + (size_t)t * BB * G4, w_hh5, hin, hout, cbuf,
            x + (size_t)t * BB * HH, out5 + (size_t)t * BB * HH);
    }

    // ---- Layer 6 ----
    init_state_kernel<<<(BB*HH + 1023)/1024, 1024>>>();
    gemm_xg_kernel<<<gemm_grid, 256>>>(out5, w_ih6, b_ih6, b_hh6, xg);
    for (int t = 0; t < TT; t++) {
        const float* hin  = (t & 1) ? h1 : h0;
        float*       hout = (t & 1) ? h0 : h1;
        lstm_step_kernel<<<128, 256>>>(
            xg + (size_t)t * BB * G4, w_hh6, hin, hout, cbuf,
            out5 + (size_t)t * BB * HH, out + (size_t)t * BB * HH);
    }
}